// round 1
// baseline (speedup 1.0000x reference)
#include <cuda_runtime.h>
#include <cuda_bf16.h>
#include <math.h>

// Problem constants
#define BB   2
#define TT   2048
#define HID  1024
#define HH   16
#define HKV  4
#define DD   64
#define GLR  16
#define MROWS (BB*TT)          // 4096
#define QCOLS (HH*DD)          // 1024
#define KCOLS (HKV*DD)         // 256

// ---------------- scratch buffers (device globals; no allocation) ----------
__device__ float g_q[MROWS * QCOLS];      // 16 MB
__device__ float g_k[MROWS * KCOLS];      // 4 MB
__device__ float g_v[MROWS * KCOLS];      // 4 MB
__device__ float g_glow[MROWS * GLR];
__device__ float g_gate[MROWS * KCOLS];   // 4 MB
__device__ float g_oattn[MROWS * QCOLS];  // 16 MB

// ---------------- tiled SGEMM: C = act(A[M,K] @ W[K,N]) --------------------
// BM=64, BN=64, BK=16, 256 threads, 4x4 micro-tile per thread.
#define BM 64
#define BN 64
#define BK 16

template <int ACT>  // 0 = none, 1 = relu
__global__ void sgemm_kernel(const float* __restrict__ A,
                             const float* __restrict__ W,
                             float* __restrict__ C,
                             int M, int N, int K) {
    __shared__ float As[BK][BM];
    __shared__ float Bs[BK][BN];

    const int tid = threadIdx.x;
    const int tx = tid & 15;
    const int ty = tid >> 4;
    const int row0 = blockIdx.y * BM;
    const int col0 = blockIdx.x * BN;

    float acc[4][4] = {};

    for (int k0 = 0; k0 < K; k0 += BK) {
        // Load A tile (64 rows x 16 k): 4 elements / thread
        #pragma unroll
        for (int i = 0; i < 4; i++) {
            int idx = tid + i * 256;
            int m  = idx >> 4;        // /16
            int kk = idx & 15;
            As[kk][m] = A[(size_t)(row0 + m) * K + k0 + kk];
        }
        // Load W tile (16 k x 64 cols): 4 elements / thread
        #pragma unroll
        for (int i = 0; i < 4; i++) {
            int idx = tid + i * 256;
            int kk = idx >> 6;        // /64
            int n  = idx & 63;
            int c  = col0 + n;
            Bs[kk][n] = (c < N) ? W[(size_t)(k0 + kk) * N + c] : 0.f;
        }
        __syncthreads();

        #pragma unroll
        for (int kk = 0; kk < BK; kk++) {
            float a[4], b[4];
            #pragma unroll
            for (int i = 0; i < 4; i++) a[i] = As[kk][ty * 4 + i];
            #pragma unroll
            for (int j = 0; j < 4; j++) b[j] = Bs[kk][tx * 4 + j];
            #pragma unroll
            for (int i = 0; i < 4; i++)
                #pragma unroll
                for (int j = 0; j < 4; j++)
                    acc[i][j] += a[i] * b[j];
        }
        __syncthreads();
    }

    #pragma unroll
    for (int i = 0; i < 4; i++) {
        int r = row0 + ty * 4 + i;
        #pragma unroll
        for (int j = 0; j < 4; j++) {
            int c = col0 + tx * 4 + j;
            if (c < N) {
                float val = acc[i][j];
                if (ACT == 1) val = fmaxf(val, 0.f);
                C[(size_t)r * N + c] = val;
            }
        }
    }
}

// ---------------- gate: gk = logsigmoid(glow @ Wg2 + bg2) / 16 -------------
__global__ void gate_kernel(const float* __restrict__ Wg2,
                            const float* __restrict__ bg2) {
    int row = blockIdx.x;
    __shared__ float gl[GLR];
    if (threadIdx.x < GLR) gl[threadIdx.x] = g_glow[row * GLR + threadIdx.x];
    __syncthreads();
    int c = threadIdx.x;  // 0..255
    float x = bg2[c];
    #pragma unroll
    for (int j = 0; j < GLR; j++) x += gl[j] * Wg2[j * KCOLS + c];
    // numerically stable log-sigmoid
    float ls = fminf(x, 0.f) - log1pf(__expf(-fabsf(x)));
    g_gate[row * KCOLS + c] = ls * (1.f / 16.f);
}

// ---------------- GLA recurrence ------------------------------------------
// One block per (b, kv-head). State S[64,64] is shared by the 4 q-heads of
// the group; outputs for all 4 q-heads computed from one state.
// Thread layout: 8 warps; within a warp lanes 4v..4v+3 own column (warp*8+v),
// split into 4 k-groups of 16 rows kept in registers.
__global__ void gla_recurrence_kernel(const float* __restrict__ unused) {
    const int blk = blockIdx.x;           // 0..7
    const int b  = blk >> 2;
    const int hk = blk & 3;
    const int tid  = threadIdx.x;
    const int lane = tid & 31;
    const int warp = tid >> 5;
    const int vcol  = warp * 8 + (lane >> 2);
    const int kg    = lane & 3;
    const int kbase = kg * 16;

    __shared__ float sk[64], sdec[64], sv[64], sq[256];

    float S[16];
    #pragma unroll
    for (int r = 0; r < 16; r++) S[r] = 0.f;

    const float scale = 0.125f;  // D^-0.5
    const size_t baseq = (size_t)b * TT * QCOLS;
    const size_t basek = (size_t)b * TT * KCOLS;

    for (int t = 0; t < TT; t++) {
        const size_t rk = basek + (size_t)t * KCOLS + hk * 64;
        if (tid < 64)        sk[tid]        = g_k[rk + tid];
        else if (tid < 128)  sdec[tid - 64] = __expf(g_gate[rk + tid - 64]);
        else if (tid < 192)  sv[tid - 128]  = g_v[rk + tid - 128];
        sq[tid] = g_q[baseq + (size_t)t * QCOLS + hk * 256 + tid] * scale;
        __syncthreads();

        const float vv = sv[vcol];
        float a0 = 0.f, a1 = 0.f, a2 = 0.f, a3 = 0.f;
        #pragma unroll
        for (int r = 0; r < 16; r++) {
            float s = sdec[kbase + r] * S[r] + sk[kbase + r] * vv;
            S[r] = s;
            a0 += sq[      kbase + r] * s;
            a1 += sq[ 64 + kbase + r] * s;
            a2 += sq[128 + kbase + r] * s;
            a3 += sq[192 + kbase + r] * s;
        }
        // reduce over the 4 k-groups (lanes 4v..4v+3)
        a0 += __shfl_xor_sync(0xffffffffu, a0, 1);
        a0 += __shfl_xor_sync(0xffffffffu, a0, 2);
        a1 += __shfl_xor_sync(0xffffffffu, a1, 1);
        a1 += __shfl_xor_sync(0xffffffffu, a1, 2);
        a2 += __shfl_xor_sync(0xffffffffu, a2, 1);
        a2 += __shfl_xor_sync(0xffffffffu, a2, 2);
        a3 += __shfl_xor_sync(0xffffffffu, a3, 1);
        a3 += __shfl_xor_sync(0xffffffffu, a3, 2);
        if (kg == 0) {
            const size_t ob = baseq + (size_t)t * QCOLS + hk * 256;
            g_oattn[ob +   0 + vcol] = a0;
            g_oattn[ob +  64 + vcol] = a1;
            g_oattn[ob + 128 + vcol] = a2;
            g_oattn[ob + 192 + vcol] = a3;
        }
        __syncthreads();
    }
    (void)unused;
}

// ---------------- per-head RMSNorm (in place on g_oattn) -------------------
__global__ void rmsnorm_kernel(const float* __restrict__ w) {
    const int warp = threadIdx.x >> 5;
    const int lane = threadIdx.x & 31;
    const size_t row = (size_t)blockIdx.x * 8 + warp;  // over B*T*H rows
    float x0 = g_oattn[row * 64 + lane];
    float x1 = g_oattn[row * 64 + lane + 32];
    float ss = x0 * x0 + x1 * x1;
    #pragma unroll
    for (int off = 16; off; off >>= 1) ss += __shfl_xor_sync(0xffffffffu, ss, off);
    float r = rsqrtf(ss * (1.f / 64.f) + 1e-6f);
    g_oattn[row * 64 + lane]      = w[lane]      * x0 * r;
    g_oattn[row * 64 + lane + 32] = w[lane + 32] * x1 * r;
}

// ---------------- launch ----------------------------------------------------
extern "C" void kernel_launch(void* const* d_in, const int* in_sizes, int n_in,
                              void* d_out, int out_size) {
    const float* hs  = (const float*)d_in[0];
    const float* Wq  = (const float*)d_in[1];
    const float* Wk  = (const float*)d_in[2];
    const float* Wv  = (const float*)d_in[3];
    const float* Wo  = (const float*)d_in[4];
    const float* Wg1 = (const float*)d_in[5];
    const float* Wg2 = (const float*)d_in[6];
    const float* bg2 = (const float*)d_in[7];
    const float* gnw = (const float*)d_in[8];
    float* out = (float*)d_out;

    float *pq, *pk, *pv, *pglow, *poattn;
    cudaGetSymbolAddress((void**)&pq,     g_q);
    cudaGetSymbolAddress((void**)&pk,     g_k);
    cudaGetSymbolAddress((void**)&pv,     g_v);
    cudaGetSymbolAddress((void**)&pglow,  g_glow);
    cudaGetSymbolAddress((void**)&poattn, g_oattn);

    // projections
    sgemm_kernel<1><<<dim3(QCOLS / BN, MROWS / BM), 256>>>(hs, Wq, pq,    MROWS, QCOLS, HID);
    sgemm_kernel<1><<<dim3(KCOLS / BN, MROWS / BM), 256>>>(hs, Wk, pk,    MROWS, KCOLS, HID);
    sgemm_kernel<0><<<dim3(KCOLS / BN, MROWS / BM), 256>>>(hs, Wv, pv,    MROWS, KCOLS, HID);
    sgemm_kernel<0><<<dim3(1,          MROWS / BM), 256>>>(hs, Wg1, pglow, MROWS, GLR,  HID);

    // gate
    gate_kernel<<<MROWS, 256>>>(Wg2, bg2);

    // recurrence (8 blocks: B * HKV)
    gla_recurrence_kernel<<<BB * HKV, 256>>>(nullptr);

    // per-head RMSNorm over D=64 (B*T*H = 65536 rows, 8 rows / block)
    rmsnorm_kernel<<<(MROWS * HH) / 8, 256>>>(gnw);

    // output projection
    sgemm_kernel<0><<<dim3(HID / BN, MROWS / BM), 256>>>(poattn, Wo, out, MROWS, HID, HID);
}

// round 2
// speedup vs baseline: 4.1978x; 4.1978x over previous
#include <cuda_runtime.h>
#include <math.h>

#define BB   2
#define TT   2048
#define HID  1024
#define HH   16
#define HKV  4
#define MROWS  (BB*TT)          // 4096
#define QCOLS  1024
#define KVCOLS 512

// ---------------- scratch (device globals; no allocation) ------------------
__device__ float g_q[MROWS * QCOLS];       // relu(hs@Wq)
__device__ float g_kv[MROWS * KVCOLS];     // [relu(hs@Wk) | hs@Wv]
__device__ float g_dec[MROWS * 256];       // exp(logsigmoid(gate)/16)
__device__ float g_oattn[MROWS * QCOLS];   // attention out (then normed)
__device__ float g_Wkv[HID * KVCOLS];      // concat(Wk, Wv)

// ---------------- tf32 mma helpers -----------------------------------------
__device__ __forceinline__ unsigned f2tf(float x) {
    unsigned r; asm("cvt.rna.tf32.f32 %0, %1;" : "=r"(r) : "f"(x)); return r;
}
__device__ __forceinline__ void mma_tf32(float* c, const unsigned* a,
                                         unsigned b0, unsigned b1) {
    asm volatile(
        "mma.sync.aligned.m16n8k8.row.col.f32.tf32.tf32.f32 "
        "{%0,%1,%2,%3},{%4,%5,%6,%7},{%8,%9},{%0,%1,%2,%3};"
        : "+f"(c[0]), "+f"(c[1]), "+f"(c[2]), "+f"(c[3])
        : "r"(a[0]), "r"(a[1]), "r"(a[2]), "r"(a[3]), "r"(b0), "r"(b1));
}

// ---------------- tf32 tensor-core GEMM: C = act(A[M,K] @ B[K,N]) ----------
// BM=128, BN=128, BK=16, 256 threads (8 warps: 4 along M x 2 along N).
// Warp tile 32x64 = 2 m16-tiles x 8 n8-tiles of m16n8k8. Double-buffered smem.
#define GBM 128
#define GBN 128
#define GBK 16
#define LDA 20     // pad: bank-conflict-free A fragment reads
#define LDB 136    // pad: bank-conflict-free B fragment reads

__global__ void __launch_bounds__(256) mma_gemm(const float* __restrict__ A,
                                                const float* __restrict__ B,
                                                float* __restrict__ C,
                                                int M, int N, int K,
                                                int relu_limit) {
    __shared__ unsigned As[2][GBM][LDA];
    __shared__ unsigned Bs[2][GBK][LDB];

    const int tid  = threadIdx.x;
    const int lane = tid & 31;
    const int warp = tid >> 5;
    const int row0 = blockIdx.y * GBM;
    const int col0 = blockIdx.x * GBN;
    const int wm = (warp & 3) * 32;
    const int wn = (warp >> 2) * 64;

    // staging indices
    const int ar = tid >> 1, ak = (tid & 1) * 8;     // A: 128 rows x 16 k
    const int bk = tid >> 4, bn = (tid & 15) * 8;    // B: 16 k x 128 n

    float acc[2][8][4];
    #pragma unroll
    for (int i = 0; i < 2; i++)
        #pragma unroll
        for (int j = 0; j < 8; j++)
            #pragma unroll
            for (int l = 0; l < 4; l++) acc[i][j][l] = 0.f;

    float4 ag0, ag1, bg0, bg1;

    auto LDGT = [&](int kt) {
        const float* ap = A + (size_t)(row0 + ar) * K + kt * GBK + ak;
        ag0 = *(const float4*)ap;
        ag1 = *(const float4*)(ap + 4);
        const float* bp = B + (size_t)(kt * GBK + bk) * N + col0 + bn;
        bg0 = *(const float4*)bp;
        bg1 = *(const float4*)(bp + 4);
    };
    auto STST = [&](int bu) {
        *(uint4*)&As[bu][ar][ak]     = make_uint4(f2tf(ag0.x), f2tf(ag0.y), f2tf(ag0.z), f2tf(ag0.w));
        *(uint4*)&As[bu][ar][ak + 4] = make_uint4(f2tf(ag1.x), f2tf(ag1.y), f2tf(ag1.z), f2tf(ag1.w));
        *(uint4*)&Bs[bu][bk][bn]     = make_uint4(f2tf(bg0.x), f2tf(bg0.y), f2tf(bg0.z), f2tf(bg0.w));
        *(uint4*)&Bs[bu][bk][bn + 4] = make_uint4(f2tf(bg1.x), f2tf(bg1.y), f2tf(bg1.z), f2tf(bg1.w));
    };
    auto COMP = [&](int bu) {
        #pragma unroll
        for (int ks = 0; ks < 2; ks++) {
            unsigned a[2][4];
            #pragma unroll
            for (int mt = 0; mt < 2; mt++) {
                int r  = wm + mt * 16 + (lane >> 2);
                int cb = ks * 8 + (lane & 3);
                a[mt][0] = As[bu][r][cb];
                a[mt][1] = As[bu][r + 8][cb];
                a[mt][2] = As[bu][r][cb + 4];
                a[mt][3] = As[bu][r + 8][cb + 4];
            }
            #pragma unroll
            for (int nt = 0; nt < 8; nt++) {
                int nc = wn + nt * 8 + (lane >> 2);
                unsigned b0 = Bs[bu][ks * 8 + (lane & 3)][nc];
                unsigned b1 = Bs[bu][ks * 8 + (lane & 3) + 4][nc];
                mma_tf32(acc[0][nt], a[0], b0, b1);
                mma_tf32(acc[1][nt], a[1], b0, b1);
            }
        }
    };

    const int NTILES = K / GBK;
    LDGT(0); STST(0);
    __syncthreads();
    for (int kt = 0; kt < NTILES; kt++) {
        if (kt + 1 < NTILES) LDGT(kt + 1);
        COMP(kt & 1);
        if (kt + 1 < NTILES) STST((kt + 1) & 1);
        __syncthreads();
    }

    #pragma unroll
    for (int mt = 0; mt < 2; mt++) {
        #pragma unroll
        for (int nt = 0; nt < 8; nt++) {
            int r  = row0 + wm + mt * 16 + (lane >> 2);
            int cc = col0 + wn + nt * 8 + (lane & 3) * 2;
            float v0 = acc[mt][nt][0], v1 = acc[mt][nt][1];
            float v2 = acc[mt][nt][2], v3 = acc[mt][nt][3];
            if (cc < relu_limit) {
                v0 = fmaxf(v0, 0.f); v1 = fmaxf(v1, 0.f);
                v2 = fmaxf(v2, 0.f); v3 = fmaxf(v3, 0.f);
            }
            *(float2*)&C[(size_t)r * N + cc]       = make_float2(v0, v1);
            *(float2*)&C[(size_t)(r + 8) * N + cc] = make_float2(v2, v3);
        }
    }
}

// ---------------- weight concat: g_Wkv = [Wk | Wv] --------------------------
__global__ void concat_w(const float* __restrict__ Wk, const float* __restrict__ Wv) {
    int i = blockIdx.x * 256 + threadIdx.x;
    if (i < HID * KVCOLS) {
        int k = i >> 9, n = i & 511;
        g_Wkv[i] = (n < 256) ? Wk[k * 256 + n] : Wv[k * 256 + n - 256];
    }
}

// ---------------- fused gate: decay = exp(logsigmoid(hs@Wg1@Wg2+b)/16) -----
__global__ void __launch_bounds__(128) gate_kernel(const float* __restrict__ hs,
                                                   const float* __restrict__ Wg1,
                                                   const float* __restrict__ Wg2,
                                                   const float* __restrict__ bg2) {
    const int row = blockIdx.x;
    const int tid = threadIdx.x;
    const int s = tid >> 4, c = tid & 15;   // 8 k-slices x 16 cols

    const float* hrow = hs + (size_t)row * HID + s * 128;
    float part = 0.f;
    #pragma unroll 4
    for (int i = 0; i < 128; i++)
        part += hrow[i] * Wg1[(size_t)(s * 128 + i) * 16 + c];

    __shared__ float ps[8][16];
    __shared__ float glow[16];
    ps[s][c] = part;
    __syncthreads();
    if (tid < 16) {
        float g = 0.f;
        #pragma unroll
        for (int j = 0; j < 8; j++) g += ps[j][tid];
        glow[tid] = g;
    }
    __syncthreads();

    #pragma unroll
    for (int c2 = tid; c2 < 256; c2 += 128) {
        float x = bg2[c2];
        #pragma unroll
        for (int j = 0; j < 16; j++) x += glow[j] * Wg2[j * 256 + c2];
        float ls = fminf(x, 0.f) - log1pf(__expf(-fabsf(x)));
        g_dec[(size_t)row * 256 + c2] = __expf(ls * 0.0625f);
    }
}

// ---------------- GLA recurrence --------------------------------------------
// 64 blocks = 8 (b,hk) groups x 8 v-chunks (8 cols each). 128 threads:
// v = tid>>4 (8 v-cols), kg = tid&15 (16 k-groups of 4 rows, state in regs).
// 4-stage cp.async ring, ONE barrier per step.
__device__ __forceinline__ void cp16(void* smem, const void* g) {
    unsigned s = (unsigned)__cvta_generic_to_shared(smem);
    asm volatile("cp.async.cg.shared.global [%0], [%1], 16;" :: "r"(s), "l"(g));
}
__device__ __forceinline__ void cp8(void* smem, const void* g) {
    unsigned s = (unsigned)__cvta_generic_to_shared(smem);
    asm volatile("cp.async.ca.shared.global [%0], [%1], 8;" :: "r"(s), "l"(g));
}
__device__ __forceinline__ void cp_commit() { asm volatile("cp.async.commit_group;"); }
__device__ __forceinline__ void cp_wait2()  { asm volatile("cp.async.wait_group 2;"); }

__global__ void __launch_bounds__(128) gla_kernel() {
    const int grp = blockIdx.x >> 3;         // 0..7: (b, hk)
    const int vc  = blockIdx.x & 7;          // v chunk
    const int b   = grp >> 2, hk = grp & 3;
    const int tid = threadIdx.x;
    const int v   = tid >> 4;                // 0..7
    const int kg  = tid & 15;                // 0..15 (4 rows each)

    __shared__ __align__(16) float s_k[4][64];
    __shared__ __align__(16) float s_d[4][64];
    __shared__ __align__(16) float s_v[4][8];
    __shared__ __align__(16) float s_q[4][256];

    const float* gq = g_q   + (size_t)b * TT * QCOLS  + hk * 256;
    const float* gk = g_kv  + (size_t)b * TT * KVCOLS + hk * 64;
    const float* gv = gk + 256 + vc * 8;     // v part of same row
    const float* gd = g_dec + (size_t)b * TT * 256    + hk * 64;
    float* go = g_oattn + (size_t)b * TT * QCOLS + hk * 256 + vc * 8 + v;

    auto ISSUE = [&](int t) {
        int st = t & 3;
        if (tid < 16)       cp16(&s_k[st][tid * 4],        gk + (size_t)t * KVCOLS + tid * 4);
        else if (tid < 32)  cp16(&s_d[st][(tid - 16) * 4], gd + (size_t)t * 256 + (tid - 16) * 4);
        else if (tid < 34)  cp16(&s_v[st][(tid - 32) * 4], gv + (size_t)t * KVCOLS + (tid - 32) * 4);
        cp8(&s_q[st][tid * 2], gq + (size_t)t * QCOLS + tid * 2);
        cp_commit();
    };

    ISSUE(0); ISSUE(1); ISSUE(2);

    float S0 = 0.f, S1 = 0.f, S2 = 0.f, S3 = 0.f;

    for (int t = 0; t < TT; t++) {
        const int st = t & 3;
        cp_wait2();
        __syncthreads();
        if (t + 3 < TT) ISSUE(t + 3); else cp_commit();

        const float4 kk = ((const float4*)s_k[st])[kg];
        const float4 dd = ((const float4*)s_d[st])[kg];
        const float  vv = s_v[st][v];
        S0 = fmaf(dd.x, S0, kk.x * vv);
        S1 = fmaf(dd.y, S1, kk.y * vv);
        S2 = fmaf(dd.z, S2, kk.z * vv);
        S3 = fmaf(dd.w, S3, kk.w * vv);

        const float4* q4 = (const float4*)s_q[st];
        const float4 q0 = q4[kg], q1 = q4[16 + kg], q2 = q4[32 + kg], q3 = q4[48 + kg];
        float a0 = q0.x * S0 + q0.y * S1 + q0.z * S2 + q0.w * S3;
        float a1 = q1.x * S0 + q1.y * S1 + q1.z * S2 + q1.w * S3;
        float a2 = q2.x * S0 + q2.y * S1 + q2.z * S2 + q2.w * S3;
        float a3 = q3.x * S0 + q3.y * S1 + q3.z * S2 + q3.w * S3;

        #pragma unroll
        for (int off = 1; off < 16; off <<= 1) {
            a0 += __shfl_xor_sync(0xffffffffu, a0, off);
            a1 += __shfl_xor_sync(0xffffffffu, a1, off);
            a2 += __shfl_xor_sync(0xffffffffu, a2, off);
            a3 += __shfl_xor_sync(0xffffffffu, a3, off);
        }
        if (kg == 0) {
            float* o = go + (size_t)t * QCOLS;
            o[0]   = a0 * 0.125f;
            o[64]  = a1 * 0.125f;
            o[128] = a2 * 0.125f;
            o[192] = a3 * 0.125f;
        }
    }
}

// ---------------- per-head RMSNorm (in place on g_oattn) --------------------
__global__ void rmsnorm_kernel(const float* __restrict__ w) {
    const int warp = threadIdx.x >> 5;
    const int lane = threadIdx.x & 31;
    const size_t row = (size_t)blockIdx.x * 8 + warp;   // B*T*H rows
    float x0 = g_oattn[row * 64 + lane];
    float x1 = g_oattn[row * 64 + lane + 32];
    float ss = x0 * x0 + x1 * x1;
    #pragma unroll
    for (int off = 16; off; off >>= 1) ss += __shfl_xor_sync(0xffffffffu, ss, off);
    float r = rsqrtf(ss * (1.f / 64.f) + 1e-6f);
    g_oattn[row * 64 + lane]      = w[lane]      * x0 * r;
    g_oattn[row * 64 + lane + 32] = w[lane + 32] * x1 * r;
}

// ---------------- launch -----------------------------------------------------
extern "C" void kernel_launch(void* const* d_in, const int* in_sizes, int n_in,
                              void* d_out, int out_size) {
    const float* hs  = (const float*)d_in[0];
    const float* Wq  = (const float*)d_in[1];
    const float* Wk  = (const float*)d_in[2];
    const float* Wv  = (const float*)d_in[3];
    const float* Wo  = (const float*)d_in[4];
    const float* Wg1 = (const float*)d_in[5];
    const float* Wg2 = (const float*)d_in[6];
    const float* bg2 = (const float*)d_in[7];
    const float* gnw = (const float*)d_in[8];
    float* out = (float*)d_out;

    float *pq, *pkv, *poattn, *pwkv;
    cudaGetSymbolAddress((void**)&pq,     g_q);
    cudaGetSymbolAddress((void**)&pkv,    g_kv);
    cudaGetSymbolAddress((void**)&poattn, g_oattn);
    cudaGetSymbolAddress((void**)&pwkv,   g_Wkv);

    concat_w<<<(HID * KVCOLS + 255) / 256, 256>>>(Wk, Wv);

    // q = relu(hs @ Wq)
    mma_gemm<<<dim3(QCOLS / GBN, MROWS / GBM), 256>>>(hs, Wq, pq, MROWS, QCOLS, HID, QCOLS);
    // kv = [relu(hs @ Wk) | hs @ Wv]
    mma_gemm<<<dim3(KVCOLS / GBN, MROWS / GBM), 256>>>(hs, pwkv, pkv, MROWS, KVCOLS, HID, 256);
    // decay
    gate_kernel<<<MROWS, 128>>>(hs, Wg1, Wg2, bg2);
    // recurrence
    gla_kernel<<<64, 128>>>();
    // rmsnorm
    rmsnorm_kernel<<<(MROWS * HH) / 8, 256>>>(gnw);
    // out = oattn @ Wo
    mma_gemm<<<dim3(HID / GBN, MROWS / GBM), 256>>>(poattn, Wo, out, MROWS, HID, QCOLS, 0);
}

// round 3
// speedup vs baseline: 8.3039x; 1.9782x over previous
#include <cuda_runtime.h>
#include <math.h>

#define BB   2
#define TT   2048
#define HID  1024
#define HH   16
#define HKV  4
#define MROWS  (BB*TT)          // 4096
#define QCOLS  1024
#define KVCOLS 512
#define NCHUNK 32               // T / 64

// ---------------- scratch (device globals; no allocation) ------------------
__device__ float g_q[MROWS * QCOLS];       // relu(hs@Wq) -> qe (in place)
__device__ float g_kv[MROWS * KVCOLS];     // [relu(hs@Wk)->ke | hs@Wv]
__device__ float g_lg[MROWS * 256];        // log decay = logsigmoid(gate)/16
__device__ float g_oattn[MROWS * QCOLS];   // normed attention out
__device__ float g_Wkv[HID * KVCOLS];      // concat(Wk, Wv)
__device__ float g_S[8 * NCHUNK * 64 * 64];// per-chunk entering states (4MB)
__device__ float g_dl[8 * NCHUNK * 64];    // exp(b_last) per group/chunk/d

// ---------------- tf32 mma helpers -----------------------------------------
__device__ __forceinline__ unsigned f2tf(float x) {
    unsigned r; asm("cvt.rna.tf32.f32 %0, %1;" : "=r"(r) : "f"(x)); return r;
}
__device__ __forceinline__ void mma_tf32(float* c, const unsigned* a,
                                         unsigned b0, unsigned b1) {
    asm volatile(
        "mma.sync.aligned.m16n8k8.row.col.f32.tf32.tf32.f32 "
        "{%0,%1,%2,%3},{%4,%5,%6,%7},{%8,%9},{%0,%1,%2,%3};"
        : "+f"(c[0]), "+f"(c[1]), "+f"(c[2]), "+f"(c[3])
        : "r"(a[0]), "r"(a[1]), "r"(a[2]), "r"(a[3]), "r"(b0), "r"(b1));
}

// ---------------- tf32 tensor-core GEMM: C = act(A[M,K] @ B[K,N]) ----------
#define GBM 128
#define GBN 128
#define GBK 16
#define LDA 20
#define LDB 136

__global__ void __launch_bounds__(256) mma_gemm(const float* __restrict__ A,
                                                const float* __restrict__ B,
                                                float* __restrict__ C,
                                                int M, int N, int K,
                                                int relu_limit) {
    __shared__ unsigned As[2][GBM][LDA];
    __shared__ unsigned Bs[2][GBK][LDB];

    const int tid  = threadIdx.x;
    const int lane = tid & 31;
    const int warp = tid >> 5;
    const int row0 = blockIdx.y * GBM;
    const int col0 = blockIdx.x * GBN;
    const int wm = (warp & 3) * 32;
    const int wn = (warp >> 2) * 64;

    const int ar = tid >> 1, ak = (tid & 1) * 8;
    const int bk = tid >> 4, bn = (tid & 15) * 8;

    float acc[2][8][4];
    #pragma unroll
    for (int i = 0; i < 2; i++)
        #pragma unroll
        for (int j = 0; j < 8; j++)
            #pragma unroll
            for (int l = 0; l < 4; l++) acc[i][j][l] = 0.f;

    float4 ag0, ag1, bg0, bg1;

    auto LDGT = [&](int kt) {
        const float* ap = A + (size_t)(row0 + ar) * K + kt * GBK + ak;
        ag0 = *(const float4*)ap;
        ag1 = *(const float4*)(ap + 4);
        const float* bp = B + (size_t)(kt * GBK + bk) * N + col0 + bn;
        bg0 = *(const float4*)bp;
        bg1 = *(const float4*)(bp + 4);
    };
    auto STST = [&](int bu) {
        *(uint4*)&As[bu][ar][ak]     = make_uint4(f2tf(ag0.x), f2tf(ag0.y), f2tf(ag0.z), f2tf(ag0.w));
        *(uint4*)&As[bu][ar][ak + 4] = make_uint4(f2tf(ag1.x), f2tf(ag1.y), f2tf(ag1.z), f2tf(ag1.w));
        *(uint4*)&Bs[bu][bk][bn]     = make_uint4(f2tf(bg0.x), f2tf(bg0.y), f2tf(bg0.z), f2tf(bg0.w));
        *(uint4*)&Bs[bu][bk][bn + 4] = make_uint4(f2tf(bg1.x), f2tf(bg1.y), f2tf(bg1.z), f2tf(bg1.w));
    };
    auto COMP = [&](int bu) {
        #pragma unroll
        for (int ks = 0; ks < 2; ks++) {
            unsigned a[2][4];
            #pragma unroll
            for (int mt = 0; mt < 2; mt++) {
                int r  = wm + mt * 16 + (lane >> 2);
                int cb = ks * 8 + (lane & 3);
                a[mt][0] = As[bu][r][cb];
                a[mt][1] = As[bu][r + 8][cb];
                a[mt][2] = As[bu][r][cb + 4];
                a[mt][3] = As[bu][r + 8][cb + 4];
            }
            #pragma unroll
            for (int nt = 0; nt < 8; nt++) {
                int nc = wn + nt * 8 + (lane >> 2);
                unsigned b0 = Bs[bu][ks * 8 + (lane & 3)][nc];
                unsigned b1 = Bs[bu][ks * 8 + (lane & 3) + 4][nc];
                mma_tf32(acc[0][nt], a[0], b0, b1);
                mma_tf32(acc[1][nt], a[1], b0, b1);
            }
        }
    };

    const int NTILES = K / GBK;
    LDGT(0); STST(0);
    __syncthreads();
    for (int kt = 0; kt < NTILES; kt++) {
        if (kt + 1 < NTILES) LDGT(kt + 1);
        COMP(kt & 1);
        if (kt + 1 < NTILES) STST((kt + 1) & 1);
        __syncthreads();
    }

    #pragma unroll
    for (int mt = 0; mt < 2; mt++) {
        #pragma unroll
        for (int nt = 0; nt < 8; nt++) {
            int r  = row0 + wm + mt * 16 + (lane >> 2);
            int cc = col0 + wn + nt * 8 + (lane & 3) * 2;
            float v0 = acc[mt][nt][0], v1 = acc[mt][nt][1];
            float v2 = acc[mt][nt][2], v3 = acc[mt][nt][3];
            if (cc < relu_limit) {
                v0 = fmaxf(v0, 0.f); v1 = fmaxf(v1, 0.f);
                v2 = fmaxf(v2, 0.f); v3 = fmaxf(v3, 0.f);
            }
            *(float2*)&C[(size_t)r * N + cc]       = make_float2(v0, v1);
            *(float2*)&C[(size_t)(r + 8) * N + cc] = make_float2(v2, v3);
        }
    }
}

// ---------------- weight concat: g_Wkv = [Wk | Wv] --------------------------
__global__ void concat_w(const float* __restrict__ Wk, const float* __restrict__ Wv) {
    int i = blockIdx.x * 256 + threadIdx.x;
    if (i < HID * KVCOLS) {
        int k = i >> 9, n = i & 511;
        g_Wkv[i] = (n < 256) ? Wk[k * 256 + n] : Wv[k * 256 + n - 256];
    }
}

// ---------------- gate: lg = logsigmoid(hs@Wg1@Wg2+b)/16 -------------------
__global__ void __launch_bounds__(128) gate_kernel(const float* __restrict__ hs,
                                                   const float* __restrict__ Wg1,
                                                   const float* __restrict__ Wg2,
                                                   const float* __restrict__ bg2) {
    const int row = blockIdx.x;
    const int tid = threadIdx.x;
    const int s = tid >> 4, c = tid & 15;

    const float* hrow = hs + (size_t)row * HID + s * 128;
    float part = 0.f;
    #pragma unroll 4
    for (int i = 0; i < 128; i++)
        part += hrow[i] * Wg1[(size_t)(s * 128 + i) * 16 + c];

    __shared__ float ps[8][16];
    __shared__ float glow[16];
    ps[s][c] = part;
    __syncthreads();
    if (tid < 16) {
        float g = 0.f;
        #pragma unroll
        for (int j = 0; j < 8; j++) g += ps[j][tid];
        glow[tid] = g;
    }
    __syncthreads();

    #pragma unroll
    for (int c2 = tid; c2 < 256; c2 += 128) {
        float x = bg2[c2];
        #pragma unroll
        for (int j = 0; j < 16; j++) x += glow[j] * Wg2[j * 256 + c2];
        float ls = fminf(x, 0.f) - log1pf(__expf(-fabsf(x)));
        g_lg[(size_t)row * 256 + c2] = ls * 0.0625f;
    }
}

// ---------------- Phase A: cumsum decays; scale q,k in place ---------------
// q <- q * exp(b_t) * scale ; k <- k * exp(-b_t) ; dl = exp(b_last)
__global__ void __launch_bounds__(64) phaseA_kernel() {
    const int c   = blockIdx.x & 31;
    const int grp = blockIdx.x >> 5;     // b*4+hk
    const int b = grp >> 2, hk = grp & 3;
    const int d = threadIdx.x;
    float bacc = 0.f;
    const size_t row0 = (size_t)b * TT + c * 64;
    for (int t = 0; t < 64; t++) {
        const size_t r = row0 + t;
        bacc += g_lg[r * 256 + hk * 64 + d];
        const float e  = __expf(bacc) * 0.125f;   // fold scale
        const float em = __expf(-bacc);
        const size_t qoff = r * 1024 + hk * 256 + d;
        g_q[qoff]       *= e;
        g_q[qoff + 64]  *= e;
        g_q[qoff + 128] *= e;
        g_q[qoff + 192] *= e;
        g_kv[r * 512 + hk * 64 + d] *= em;
    }
    g_dl[(grp * 32 + c) * 64 + d] = __expf(bacc);
}

// ---------------- Phase B: propagate states across chunks ------------------
// S_new = dl ⊙ (S_old + sum_t ke_t ⊗ v_t). Writes entering state per chunk.
// 64 blocks = 8 groups x 8 v-chunks (8 cols). 128 threads: kg=tid>>3 (4 rows), v=tid&7.
__global__ void __launch_bounds__(128) phaseB_kernel() {
    const int grp = blockIdx.x >> 3;
    const int vc  = blockIdx.x & 7;
    const int b = grp >> 2, hk = grp & 3;
    const int tid = threadIdx.x;
    const int v  = tid & 7;
    const int kg = tid >> 3;            // 0..15
    __shared__ float ke_s[64][64];
    __shared__ float v_s[64][8];
    float S0 = 0.f, S1 = 0.f, S2 = 0.f, S3 = 0.f;

    for (int c = 0; c < NCHUNK; c++) {
        const size_t row0 = (size_t)b * TT + c * 64;
        __syncthreads();
        #pragma unroll
        for (int i = tid; i < 64 * 16; i += 128) {
            int t = i >> 4, dq = i & 15;
            ((float4*)ke_s[t])[dq] = *(const float4*)&g_kv[(row0 + t) * 512 + hk * 64 + dq * 4];
        }
        {
            int t = tid >> 1, q4 = tid & 1;
            if (tid < 128)
                ((float4*)v_s[t])[q4] = *(const float4*)&g_kv[(row0 + t) * 512 + 256 + hk * 64 + vc * 8 + q4 * 4];
        }
        __syncthreads();

        // write entering state for this chunk
        const size_t sb_ = ((size_t)(grp * 32 + c) * 64 + kg * 4) * 64 + vc * 8 + v;
        g_S[sb_]       = S0;
        g_S[sb_ + 64]  = S1;
        g_S[sb_ + 128] = S2;
        g_S[sb_ + 192] = S3;

        #pragma unroll 4
        for (int t = 0; t < 64; t++) {
            const float4 kk = ((const float4*)ke_s[t])[kg];
            const float  vv = v_s[t][v];
            S0 = fmaf(kk.x, vv, S0);
            S1 = fmaf(kk.y, vv, S1);
            S2 = fmaf(kk.z, vv, S2);
            S3 = fmaf(kk.w, vv, S3);
        }
        const float4 dl4 = *(const float4*)&g_dl[(grp * 32 + c) * 64 + kg * 4];
        S0 *= dl4.x; S1 *= dl4.y; S2 *= dl4.z; S3 *= dl4.w;
    }
}

// ---------------- Phase C: intra-chunk attention + inter term + RMSNorm ----
// Per block: (group, head, chunk). O = tril(qe@ke^T)@v + qe@S_c, then RMSNorm.
__global__ void __launch_bounds__(256) phaseC_kernel(const float* __restrict__ gnw) {
    extern __shared__ float smem[];
    float* qe_s = smem;            // [64][65]
    float* keA  = smem + 4160;     // [64][65]  ke, then reused for A
    float* v_s  = smem + 8320;     // [64][64]
    float* S_s  = smem + 12416;    // [64][64]

    const int c   = blockIdx.x & 31;
    const int h   = (blockIdx.x >> 5) & 3;
    const int grp = blockIdx.x >> 7;          // b*4+hk
    const int b = grp >> 2, hk = grp & 3;
    const int tid = threadIdx.x;
    const int ty = tid >> 4, tx = tid & 15;
    const size_t row0 = (size_t)b * TT + c * 64;

    for (int i = tid; i < 4096; i += 256) {
        int t = i >> 6, d = i & 63;
        qe_s[t * 65 + d] = g_q [(row0 + t) * 1024 + hk * 256 + h * 64 + d];
        keA [t * 65 + d] = g_kv[(row0 + t) * 512 + hk * 64 + d];
        v_s [t * 64 + d] = g_kv[(row0 + t) * 512 + 256 + hk * 64 + d];
        S_s [t * 64 + d] = g_S [((size_t)(grp * 32 + c) * 64 + t) * 64 + d];
    }
    __syncthreads();

    // A[t][s] = qe_t . ke_s (inner over d)
    float A[4][4] = {};
    for (int d = 0; d < 64; d++) {
        float a0 = qe_s[(ty * 4 + 0) * 65 + d];
        float a1 = qe_s[(ty * 4 + 1) * 65 + d];
        float a2 = qe_s[(ty * 4 + 2) * 65 + d];
        float a3 = qe_s[(ty * 4 + 3) * 65 + d];
        float b0 = keA[(tx * 4 + 0) * 65 + d];
        float b1 = keA[(tx * 4 + 1) * 65 + d];
        float b2 = keA[(tx * 4 + 2) * 65 + d];
        float b3 = keA[(tx * 4 + 3) * 65 + d];
        A[0][0] += a0 * b0; A[0][1] += a0 * b1; A[0][2] += a0 * b2; A[0][3] += a0 * b3;
        A[1][0] += a1 * b0; A[1][1] += a1 * b1; A[1][2] += a1 * b2; A[1][3] += a1 * b3;
        A[2][0] += a2 * b0; A[2][1] += a2 * b1; A[2][2] += a2 * b2; A[2][3] += a2 * b3;
        A[3][0] += a3 * b0; A[3][1] += a3 * b1; A[3][2] += a3 * b2; A[3][3] += a3 * b3;
    }
    __syncthreads();
    // mask (causal within chunk) and store A into keA region
    #pragma unroll
    for (int i = 0; i < 4; i++) {
        int t = ty * 4 + i;
        #pragma unroll
        for (int j = 0; j < 4; j++) {
            int s = tx * 4 + j;
            keA[t * 65 + s] = (s <= t) ? A[i][j] : 0.f;
        }
    }
    __syncthreads();

    // O = A @ v + qe @ S
    float O[4][4] = {};
    for (int s = 0; s < 64; s++) {
        float a0 = keA[(ty * 4 + 0) * 65 + s];
        float a1 = keA[(ty * 4 + 1) * 65 + s];
        float a2 = keA[(ty * 4 + 2) * 65 + s];
        float a3 = keA[(ty * 4 + 3) * 65 + s];
        float4 bv = *(const float4*)&v_s[s * 64 + tx * 4];
        O[0][0] += a0 * bv.x; O[0][1] += a0 * bv.y; O[0][2] += a0 * bv.z; O[0][3] += a0 * bv.w;
        O[1][0] += a1 * bv.x; O[1][1] += a1 * bv.y; O[1][2] += a1 * bv.z; O[1][3] += a1 * bv.w;
        O[2][0] += a2 * bv.x; O[2][1] += a2 * bv.y; O[2][2] += a2 * bv.z; O[2][3] += a2 * bv.w;
        O[3][0] += a3 * bv.x; O[3][1] += a3 * bv.y; O[3][2] += a3 * bv.z; O[3][3] += a3 * bv.w;
    }
    for (int d = 0; d < 64; d++) {
        float a0 = qe_s[(ty * 4 + 0) * 65 + d];
        float a1 = qe_s[(ty * 4 + 1) * 65 + d];
        float a2 = qe_s[(ty * 4 + 2) * 65 + d];
        float a3 = qe_s[(ty * 4 + 3) * 65 + d];
        float4 bs = *(const float4*)&S_s[d * 64 + tx * 4];
        O[0][0] += a0 * bs.x; O[0][1] += a0 * bs.y; O[0][2] += a0 * bs.z; O[0][3] += a0 * bs.w;
        O[1][0] += a1 * bs.x; O[1][1] += a1 * bs.y; O[1][2] += a1 * bs.z; O[1][3] += a1 * bs.w;
        O[2][0] += a2 * bs.x; O[2][1] += a2 * bs.y; O[2][2] += a2 * bs.z; O[2][3] += a2 * bs.w;
        O[3][0] += a3 * bs.x; O[3][1] += a3 * bs.y; O[3][2] += a3 * bs.z; O[3][3] += a3 * bs.w;
    }

    // fused RMSNorm: each row t's 64 cols live on the 16 tx lanes of this ty group
    float gw0 = gnw[tx * 4 + 0], gw1 = gnw[tx * 4 + 1];
    float gw2 = gnw[tx * 4 + 2], gw3 = gnw[tx * 4 + 3];
    #pragma unroll
    for (int i = 0; i < 4; i++) {
        float ss = O[i][0] * O[i][0] + O[i][1] * O[i][1] + O[i][2] * O[i][2] + O[i][3] * O[i][3];
        ss += __shfl_xor_sync(0xffffffffu, ss, 1);
        ss += __shfl_xor_sync(0xffffffffu, ss, 2);
        ss += __shfl_xor_sync(0xffffffffu, ss, 4);
        ss += __shfl_xor_sync(0xffffffffu, ss, 8);
        float r = rsqrtf(ss * (1.f / 64.f) + 1e-6f);
        int t = ty * 4 + i;
        float4 o4 = make_float4(O[i][0] * r * gw0, O[i][1] * r * gw1,
                                O[i][2] * r * gw2, O[i][3] * r * gw3);
        *(float4*)&g_oattn[(row0 + t) * 1024 + (hk * 4 + h) * 64 + tx * 4] = o4;
    }
}

// ---------------- launch -----------------------------------------------------
extern "C" void kernel_launch(void* const* d_in, const int* in_sizes, int n_in,
                              void* d_out, int out_size) {
    const float* hs  = (const float*)d_in[0];
    const float* Wq  = (const float*)d_in[1];
    const float* Wk  = (const float*)d_in[2];
    const float* Wv  = (const float*)d_in[3];
    const float* Wo  = (const float*)d_in[4];
    const float* Wg1 = (const float*)d_in[5];
    const float* Wg2 = (const float*)d_in[6];
    const float* bg2 = (const float*)d_in[7];
    const float* gnw = (const float*)d_in[8];
    float* out = (float*)d_out;

    float *pq, *pkv, *poattn, *pwkv;
    cudaGetSymbolAddress((void**)&pq,     g_q);
    cudaGetSymbolAddress((void**)&pkv,    g_kv);
    cudaGetSymbolAddress((void**)&poattn, g_oattn);
    cudaGetSymbolAddress((void**)&pwkv,   g_Wkv);

    static int smem_set = 0;
    if (!smem_set) {
        cudaFuncSetAttribute(phaseC_kernel,
                             cudaFuncAttributeMaxDynamicSharedMemorySize, 66048);
        smem_set = 1;
    }

    concat_w<<<(HID * KVCOLS + 255) / 256, 256>>>(Wk, Wv);

    // q = relu(hs @ Wq)
    mma_gemm<<<dim3(QCOLS / GBN, MROWS / GBM), 256>>>(hs, Wq, pq, MROWS, QCOLS, HID, QCOLS);
    // kv = [relu(hs @ Wk) | hs @ Wv]
    mma_gemm<<<dim3(KVCOLS / GBN, MROWS / GBM), 256>>>(hs, pwkv, pkv, MROWS, KVCOLS, HID, 256);
    // log decays
    gate_kernel<<<MROWS, 128>>>(hs, Wg1, Wg2, bg2);
    // chunked GLA
    phaseA_kernel<<<8 * NCHUNK, 64>>>();
    phaseB_kernel<<<64, 128>>>();
    phaseC_kernel<<<8 * 4 * NCHUNK, 256, 66048>>>(gnw);
    // out = oattn @ Wo
    mma_gemm<<<dim3(HID / GBN, MROWS / GBM), 256>>>(poattn, Wo, out, MROWS, HID, QCOLS, 0);
}